// round 14
// baseline (speedup 1.0000x reference)
#include <cuda_runtime.h>
#include <cuda_fp16.h>

#define NA   3
#define NC   20
#define NCH  25      // 5 + NC
#define NT   256     // number of targets
#define TPB  64      // targets per target-block (NT/4)
#define EPSF 1e-7f
#define NWARPS_TOTAL (234 * 8)   // grid warps; finalize counts warp arrivals

// Accumulators. Zero-initialized at module load; the finalizing warp
// re-zeroes them so every graph replay starts clean.
__device__ double   g_obj[3];
__device__ float    g_corr[3];
__device__ float    g_box;
__device__ float    g_cls;
__device__ unsigned g_done;

__device__ __forceinline__ float sigmoidf(float x) {
    return 1.f / (1.f + __expf(-x));
}
// factor (1 + e^x) via MUFU
__device__ __forceinline__ float spf(float x) {
    return 1.f + __expf(x);
}
// factor (1 + e^x) via FMA-pipe exp2 bit trick (no MUFU).
// |rel err| ~1e-4, minimax (near-zero bias). Safe for x in [-20, 30].
__device__ __forceinline__ float spf_poly(float x) {
    x = fminf(fmaxf(x, -20.f), 30.f);
    const float y = x * 1.44269504088896f;     // log2(e)
    const float r = rintf(y);
    const float f = y - r;
    float p = fmaf(f, 0.0558263f, 0.2401536f);
    p = fmaf(f, p, 0.6931531f);
    p = fmaf(f, p, 0.9999993f);
    const int e = (int)r;
    const float s = __int_as_float(__float_as_int(p) + (e << 23));
    return 1.f + s;
}

__device__ __forceinline__ float warpReduceSum(float v) {
    #pragma unroll
    for (int o = 16; o > 0; o >>= 1)
        v += __shfl_xor_sync(0xffffffffu, v, o);
    return v;
}

// fp32 product of 8 factors: 6 MUFU exp + 2 FMA-pipe poly exp
__device__ __forceinline__ float prod8(float4 a, float4 b) {
    return ((spf(a.x) * spf(a.y)) * (spf(a.z) * spf_poly(a.w)))
         * ((spf(b.x) * spf(b.y)) * (spf(b.z) * spf_poly(b.w)));
}

// half2 product of 8 HALVED factors (0.5 + 0.5 e^x); log of this equals
// sum softplus - 8*ln2. h2exp: 2 exps per MUFU op. Max factor ~183 (x<=5.9),
// pairwise products <= ~33K < fp16 max: overflow-safe.
__device__ __forceinline__ float prod8_h2(float4 a, float4 b) {
    const __half2 half_h = __float2half2_rn(0.5f);
    __half2 h0 = __floats2half2_rn(a.x, a.y);
    __half2 h1 = __floats2half2_rn(a.z, a.w);
    __half2 h2 = __floats2half2_rn(b.x, b.y);
    __half2 h3 = __floats2half2_rn(b.z, b.w);
    h0 = __hfma2(h2exp(h0), half_h, half_h);
    h1 = __hfma2(h2exp(h1), half_h, half_h);
    h2 = __hfma2(h2exp(h2), half_h, half_h);
    h3 = __hfma2(h2exp(h3), half_h, half_h);
    const __half2 p01 = __hmul2(h0, h1);
    const __half2 p23 = __hmul2(h2, h3);
    const float2 f01 = __half22float2(p01);
    const float2 f23 = __half22float2(p23);
    return (f01.x * f01.y) * (f23.x * f23.y);
}

// 16-element softplus group-sum (MINUS 8*ln2, restored at finalize).
// Requires HW4 % 4 == 0 (no plane straddle).
template<int HW4>
__device__ __forceinline__ float sweep16(const float* __restrict__ p, int e16) {
    const int f4    = e16 * 4;
    const int plane = f4 / HW4;                 // constant divisor -> mul/shift
    const float4* q = (const float4*)p + f4 + (size_t)HW4 * (24 * plane + 4);
    float4 v0 = q[0], v1 = q[1], v2 = q[2], v3 = q[3];   // MLP = 4
    return __logf(prod8(v0, v1)) + __logf(prod8_h2(v2, v3));
}

__global__ void __launch_bounds__(256) fused_kernel(
    const float* __restrict__ p0,
    const float* __restrict__ p1,
    const float* __restrict__ p2,
    const float* __restrict__ tg,
    float* __restrict__ out, int out_size)
{
    const int bid = blockIdx.x;
    const int t   = threadIdx.x;
    const int lid = t & 31;

    if (bid < 36) {
        // ------- target blocks: (scale, anchor, quarter), 64 targets each -------
        __shared__ float s_t[NT * 6];
        __shared__ int   s_key[NT];
        for (int i = t; i < NT * 6; i += 256) s_t[i] = tg[i];
        __syncthreads();

        const int s = bid / 12;                 // scale
        const int a = (bid / 4) % 3;            // anchor
        const int q4 = bid & 3;                 // quarter
        const int H  = (s == 0) ? 80 : (s == 1) ? 40 : 20;
        const int W  = H;
        const int HW = H * W;
        const float* p = (s == 0) ? p0 : (s == 1) ? p1 : p2;
        const float fw = (float)W, fh = (float)H;

        // every thread computes the key for target t (full table for dedup scan)
        {
            const int   kb = (int)s_t[t * 6 + 0];
            const float kx = s_t[t * 6 + 2];
            const float ky = s_t[t * 6 + 3];
            const int kgi = (int)fminf(fmaxf(kx * fw, 0.f), fw - 1.f);
            const int kgj = (int)fminf(fmaxf(ky * fh, 0.f), fh - 1.f);
            s_key[t] = (kb << 14) | (kgj << 7) | kgi;
        }
        __syncthreads();

        float lbox = 0.f, csum = 0.f, corr = 0.f;
        if (t < TPB) {
            const int n = q4 * TPB + t;         // this thread's target
            const int   bi = (int)s_t[n * 6 + 0];
            const int   ci = (int)s_t[n * 6 + 1];
            const float cx = s_t[n * 6 + 2];
            const float cy = s_t[n * 6 + 3];
            const float tw = s_t[n * 6 + 4];
            const float th = s_t[n * 6 + 5];

            const int gi = (int)fminf(fmaxf(cx * fw, 0.f), fw - 1.f);
            const int gj = (int)fminf(fmaxf(cy * fh, 0.f), fh - 1.f);
            const int key = (bi << 14) | (gj << 7) | gi;

            const float* cellp = p + ((size_t)(bi * NA * NCH + a * NCH)) * HW
                                   + (size_t)gj * W + gi;

            // ---- issue ALL scattered loads up front (high MLP) ----
            const float x0 = cellp[0];
            const float x1 = cellp[HW];
            float xv[NC];
            #pragma unroll
            for (int c = 0; c < NC; c++) xv[c] = cellp[(size_t)(5 + c) * HW];
            const float xci = cellp[(size_t)(5 + ci) * HW];
            float c0 = 0.f, c1 = 0.f, c2v = 0.f;
            const float* op = p + ((size_t)(bi * NA * NCH)) * HW + (size_t)gj * W + gi;
            if (a == 0) {
                c0  = op[(size_t)4 * HW];
                c1  = op[(size_t)(NCH + 4) * HW];
                c2v = op[(size_t)(2 * NCH + 4) * HW];
            }

            const float sx = sigmoidf(x0);
            const float sy = sigmoidf(x1);

            const float twh = tw * fw * 0.5f;
            const float thh = th * fh * 0.5f;
            const float gif = (float)gi, gjf = (float)gj;

            const float px1 = (sx + gif - twh) / fw;
            const float py1 = (sy + gjf - thh) / fh;
            const float px2 = (sx + gif + twh) / fw;
            const float py2 = (sy + gjf + thh) / fh;

            const float tx1 = cx - tw * 0.5f;
            const float ty1 = cy - th * 0.5f;
            const float tx2 = cx + tw * 0.5f;
            const float ty2 = cy + th * 0.5f;

            // CIoU loss
            const float ix1 = fmaxf(px1, tx1), iy1 = fmaxf(py1, ty1);
            const float ix2 = fminf(px2, tx2), iy2 = fminf(py2, ty2);
            const float inter  = fmaxf(ix2 - ix1, 0.f) * fmaxf(iy2 - iy1, 0.f);
            const float area_p = (px2 - px1) * (py2 - py1);
            const float area_t = (tx2 - tx1) * (ty2 - ty1);
            const float uni = area_p + area_t - inter + EPSF;
            const float iou = inter / uni;
            const float ex1 = fminf(px1, tx1), ey1 = fminf(py1, ty1);
            const float ex2 = fmaxf(px2, tx2), ey2 = fmaxf(py2, ty2);
            const float c2  = (ex2 - ex1) * (ex2 - ex1) + (ey2 - ey1) * (ey2 - ey1) + EPSF;
            const float dxc = (px1 + px2) * 0.5f - (tx1 + tx2) * 0.5f;
            const float dyc = (py1 + py2) * 0.5f - (ty1 + ty2) * 0.5f;
            const float rho2 = dxc * dxc + dyc * dyc;
            const float pw  = fmaxf(px2 - px1, EPSF);
            const float ph  = fmaxf(py2 - py1, EPSF);
            const float twc = fmaxf(tx2 - tx1, EPSF);
            const float thc = fmaxf(ty2 - ty1, EPSF);
            const float dd  = atanf(twc / thc) - atanf(pw / ph);
            const float v   = 0.4052847345693511f * dd * dd;   // 4/pi^2
            const float alpha = v / (1.f - iou + v + EPSF);
            lbox = 1.f - (iou - rho2 / c2 - alpha * v);

            // cls BCE: [log prod(1+e^x) - x_ci] / NC  (4-way ILP product)
            float pr0 = 1.f, pr1 = 1.f, pr2 = 1.f, pr3 = 1.f;
            #pragma unroll
            for (int c = 0; c < NC; c += 4) {
                pr0 *= spf(xv[c]);
                pr1 *= spf(xv[c + 1]);
                pr2 *= spf(xv[c + 2]);
                pr3 *= spf(xv[c + 3]);
            }
            csum = (__logf((pr0 * pr1) * (pr2 * pr3)) - xci) * (1.f / (float)NC);

            // obj correction for first occurrence of this cell (all anchors)
            if (a == 0) {
                bool dup = false;
                #pragma unroll 4
                for (int m = 0; m < n; m++)
                    dup |= (s_key[m] == key);
                corr = dup ? 0.f : -(c0 + c1 + c2v);
            }
        }

        float rb = warpReduceSum(lbox);
        float rc = warpReduceSum(csum);
        float ro = warpReduceSum(corr);
        if (lid == 0 && t < TPB) {
            atomicAdd(&g_box, rb);
            atomicAdd(&g_cls, rc);
            if (a == 0) atomicAdd(&g_corr[s], ro);
        }
    } else {
        // -------- objectness softplus sweep: 16 elems (4 float4) / thread --------
        // block ranges: [36,186) sc0, [186,224) sc1, [224,234) sc2
        float gsum = 0.f;
        double* acc;
        if (bid < 186) {
            const int e16 = (bid - 36) * 256 + t;         // cap 38400: exact (150 blocks)
            gsum = sweep16<1600>(p0, e16);
            acc = &g_obj[0];
        } else if (bid < 224) {
            const int e16 = (bid - 186) * 256 + t;        // cap 9600
            if (e16 < 9600) gsum = sweep16<400>(p1, e16);
            acc = &g_obj[1];
        } else {
            const int e16 = (bid - 224) * 256 + t;        // cap 2400
            if (e16 < 2400) gsum = sweep16<100>(p2, e16);
            acc = &g_obj[2];
        }
        float wsum = warpReduceSum(gsum);
        if (lid == 0 && wsum != 0.f)
            atomicAdd(acc, (double)wsum);
    }

    // -------- warp-granular finalize: every warp's lane 0 arrives --------
    if (lid == 0) {
        __threadfence();                     // release: my REDs before arrival
        unsigned old = atomicAdd(&g_done, 1u);
        if (old == NWARPS_TOTAL - 1) {
            __threadfence();                 // acquire: observe all REDs
            const double cnt[3] = {614400.0, 153600.0, 38400.0};
            double lod = 0.0;
            for (int k = 0; k < 3; k++)
                lod += (g_obj[k] + (double)g_corr[k]) / cnt[k];
            // exactly half of each scale's elements used halved (h2) factors:
            // restore with +0.5*ln2 per scale mean = 1.5*ln2 total
            lod += 1.0397207708399179;       // 1.5 * ln(2)
            const float lo = (float)lod;
            const float lb = g_box * (1.f / 2304.f);   // N*A*3
            const float lc = g_cls * (1.f / 2304.f);
            const float total = 0.05f * lb + 1.0f * lo + 0.5f * lc;
            float vals[5] = {total, lb, lo, lc, 0.f};
            for (int i = 0; i < out_size; i++)
                out[i] = (i < 5) ? vals[i] : 0.f;
            // reset for next graph replay
            g_box = 0.f;
            g_cls = 0.f;
            for (int k = 0; k < 3; k++) { g_corr[k] = 0.f; g_obj[k] = 0.0; }
            g_done = 0u;
        }
    }
}

extern "C" void kernel_launch(void* const* d_in, const int* in_sizes, int n_in,
                              void* d_out, int out_size) {
    const float* p0 = (const float*)d_in[0];
    const float* p1 = (const float*)d_in[1];
    const float* p2 = (const float*)d_in[2];
    const float* tg = (const float*)d_in[3];
    (void)in_sizes; (void)n_in;

    // 36 target + 150 + 38 + 10 sweep = 234 blocks
    fused_kernel<<<234, 256>>>(p0, p1, p2, tg, (float*)d_out, out_size);
}

// round 16
// speedup vs baseline: 1.1006x; 1.1006x over previous
#include <cuda_runtime.h>

#define NA   3
#define NC   20
#define NCH  25      // 5 + NC
#define NT   256     // number of targets
#define TPB  64      // targets per target-block (NT/4)
#define EPSF 1e-7f

// Accumulators. Zero-initialized at module load; the finalizing block
// re-zeroes them so every graph replay starts clean.
__device__ double   g_obj[3];
__device__ float    g_corr[3];
__device__ float    g_box;
__device__ float    g_cls;
__device__ unsigned g_done;

__device__ __forceinline__ float sigmoidf(float x) {
    return 1.f / (1.f + __expf(-x));
}
// factor (1 + e^x) via MUFU
__device__ __forceinline__ float spf(float x) {
    return 1.f + __expf(x);
}
// factor (1 + e^x) via FMA-pipe exp2 bit trick (no MUFU).
// |rel err| ~1e-4, minimax (near-zero bias). Safe for x in [-20, 30].
__device__ __forceinline__ float spf_poly(float x) {
    x = fminf(fmaxf(x, -20.f), 30.f);
    const float y = x * 1.44269504088896f;     // log2(e)
    const float r = rintf(y);
    const float f = y - r;
    float p = fmaf(f, 0.0558263f, 0.2401536f);
    p = fmaf(f, p, 0.6931531f);
    p = fmaf(f, p, 0.9999993f);
    const int e = (int)r;
    const float s = __int_as_float(__float_as_int(p) + (e << 23));
    return 1.f + s;
}

__device__ __forceinline__ float warpReduceSum(float v) {
    #pragma unroll
    for (int o = 16; o > 0; o >>= 1)
        v += __shfl_xor_sync(0xffffffffu, v, o);
    return v;
}

// product of 8 factors: 6 via MUFU exp, 2 via FMA-pipe poly exp (pipe balance)
__device__ __forceinline__ float prod8(float4 a, float4 b) {
    return ((spf(a.x) * spf(a.y)) * (spf(a.z) * spf_poly(a.w)))
         * ((spf(b.x) * spf(b.y)) * (spf(b.z) * spf_poly(b.w)));
}

// 16-element softplus group-sum; requires HW4 % 4 == 0 (no plane straddle)
template<int HW4>
__device__ __forceinline__ float sweep16(const float* __restrict__ p, int e16) {
    const int f4    = e16 * 4;
    const int plane = f4 / HW4;                 // constant divisor -> mul/shift
    const float4* q = (const float4*)p + f4 + (size_t)HW4 * (24 * plane + 4);
    float4 v0 = q[0], v1 = q[1], v2 = q[2], v3 = q[3];   // MLP = 4
    return __logf(prod8(v0, v1)) + __logf(prod8(v2, v3));
}

__global__ void __launch_bounds__(256) fused_kernel(
    const float* __restrict__ p0,
    const float* __restrict__ p1,
    const float* __restrict__ p2,
    const float* __restrict__ tg,
    float* __restrict__ out, int out_size)
{
    const int bid = blockIdx.x;
    const int t   = threadIdx.x;
    const int lid = t & 31;

    if (bid < 36) {
        // ------- target blocks: (scale, anchor, quarter), 64 targets each -------
        __shared__ int s_key[NT];

        const int s = bid / 12;                 // scale
        const int a = (bid / 4) % 3;            // anchor
        const int q4 = bid & 3;                 // quarter
        const int H  = (s == 0) ? 80 : (s == 1) ? 40 : 20;
        const int W  = H;
        const int HW = H * W;
        const float* p = (s == 0) ? p0 : (s == 1) ? p1 : p2;
        const float fw = (float)W, fh = (float)H;
        const float2* tg2 = (const float2*)tg;  // 3 float2 per target (24B, 8B-aligned)

        // my work target: n = q4*64 + t (threads 0..63); load it FIRST, straight
        // from gmem, and issue every scattered gather before any barrier.
        float lbox = 0.f, csum = 0.f, corr = 0.f;
        const int n = q4 * TPB + t;

        float2 w0, w1, w2;
        int bi = 0, ci = 0, gi = 0, gj = 0, key = 0;
        const float* cellp = p;
        if (t < TPB) {
            w0 = tg2[n * 3 + 0];                // (b_idx, cls_id)
            w1 = tg2[n * 3 + 1];                // (cx, cy)
            w2 = tg2[n * 3 + 2];                // (tw, th)
            bi = (int)w0.x;
            ci = (int)w0.y;
            gi = (int)fminf(fmaxf(w1.x * fw, 0.f), fw - 1.f);
            gj = (int)fminf(fmaxf(w1.y * fh, 0.f), fh - 1.f);
            key = (bi << 14) | (gj << 7) | gi;
            cellp = p + ((size_t)(bi * NA * NCH + a * NCH)) * HW
                      + (size_t)gj * W + gi;
        }
        // ---- gathers in flight while the key table is built ----
        float x0 = 0.f, x1 = 0.f, xci = 0.f;
        float xv[NC];
        float c0 = 0.f, c1 = 0.f, c2v = 0.f;
        if (t < TPB) {
            x0 = cellp[0];
            x1 = cellp[HW];
            #pragma unroll
            for (int c = 0; c < NC; c++) xv[c] = cellp[(size_t)(5 + c) * HW];
            xci = cellp[(size_t)(5 + ci) * HW];
            if (a == 0) {
                const float* op = p + ((size_t)(bi * NA * NCH)) * HW
                                    + (size_t)gj * W + gi;
                c0  = op[(size_t)4 * HW];
                c1  = op[(size_t)(NCH + 4) * HW];
                c2v = op[(size_t)(2 * NCH + 4) * HW];
            }
        }

        // key table: thread t computes key for target t (all 256)
        {
            float2 k0 = tg2[t * 3 + 0];
            float2 k1 = tg2[t * 3 + 1];
            const int kb  = (int)k0.x;
            const int kgi = (int)fminf(fmaxf(k1.x * fw, 0.f), fw - 1.f);
            const int kgj = (int)fminf(fmaxf(k1.y * fh, 0.f), fh - 1.f);
            s_key[t] = (kb << 14) | (kgj << 7) | kgi;
        }
        __syncthreads();

        if (t < TPB) {
            const float cx = w1.x, cy = w1.y;
            const float tw = w2.x, th = w2.y;

            const float sx = sigmoidf(x0);
            const float sy = sigmoidf(x1);

            const float twh = tw * fw * 0.5f;
            const float thh = th * fh * 0.5f;
            const float gif = (float)gi, gjf = (float)gj;

            const float px1 = (sx + gif - twh) / fw;
            const float py1 = (sy + gjf - thh) / fh;
            const float px2 = (sx + gif + twh) / fw;
            const float py2 = (sy + gjf + thh) / fh;

            const float tx1 = cx - tw * 0.5f;
            const float ty1 = cy - th * 0.5f;
            const float tx2 = cx + tw * 0.5f;
            const float ty2 = cy + th * 0.5f;

            // CIoU loss
            const float ix1 = fmaxf(px1, tx1), iy1 = fmaxf(py1, ty1);
            const float ix2 = fminf(px2, tx2), iy2 = fminf(py2, ty2);
            const float inter  = fmaxf(ix2 - ix1, 0.f) * fmaxf(iy2 - iy1, 0.f);
            const float area_p = (px2 - px1) * (py2 - py1);
            const float area_t = (tx2 - tx1) * (ty2 - ty1);
            const float uni = area_p + area_t - inter + EPSF;
            const float iou = inter / uni;
            const float ex1 = fminf(px1, tx1), ey1 = fminf(py1, ty1);
            const float ex2 = fmaxf(px2, tx2), ey2 = fmaxf(py2, ty2);
            const float c2  = (ex2 - ex1) * (ex2 - ex1) + (ey2 - ey1) * (ey2 - ey1) + EPSF;
            const float dxc = (px1 + px2) * 0.5f - (tx1 + tx2) * 0.5f;
            const float dyc = (py1 + py2) * 0.5f - (ty1 + ty2) * 0.5f;
            const float rho2 = dxc * dxc + dyc * dyc;
            const float pw  = fmaxf(px2 - px1, EPSF);
            const float ph  = fmaxf(py2 - py1, EPSF);
            const float twc = fmaxf(tx2 - tx1, EPSF);
            const float thc = fmaxf(ty2 - ty1, EPSF);
            const float dd  = atanf(twc / thc) - atanf(pw / ph);
            const float v   = 0.4052847345693511f * dd * dd;   // 4/pi^2
            const float alpha = v / (1.f - iou + v + EPSF);
            lbox = 1.f - (iou - rho2 / c2 - alpha * v);

            // cls BCE: [log prod(1+e^x) - x_ci] / NC  (4-way ILP product)
            float pr0 = 1.f, pr1 = 1.f, pr2 = 1.f, pr3 = 1.f;
            #pragma unroll
            for (int c = 0; c < NC; c += 4) {
                pr0 *= spf(xv[c]);
                pr1 *= spf(xv[c + 1]);
                pr2 *= spf(xv[c + 2]);
                pr3 *= spf(xv[c + 3]);
            }
            csum = (__logf((pr0 * pr1) * (pr2 * pr3)) - xci) * (1.f / (float)NC);

            // obj correction for first occurrence of this cell (all anchors)
            if (a == 0) {
                bool dup = false;
                #pragma unroll 4
                for (int m = 0; m < n; m++)
                    dup |= (s_key[m] == key);
                corr = dup ? 0.f : -(c0 + c1 + c2v);
            }
        }

        // warps 0-1 hold all contributions; others have zeros and skip atomics
        float rb = warpReduceSum(lbox);
        float rc = warpReduceSum(csum);
        float ro = warpReduceSum(corr);
        if (lid == 0 && t < TPB) {
            atomicAdd(&g_box, rb);
            atomicAdd(&g_cls, rc);
            if (a == 0) atomicAdd(&g_corr[s], ro);
            __threadfence();   // order my REDs before the barrier
        }
        __syncthreads();       // all warps' atomics fenced before finalize
    } else {
        // -------- objectness softplus sweep: 16 elems (4 float4) / thread --------
        // block ranges: [36,186) sc0, [186,224) sc1, [224,234) sc2
        float gsum = 0.f;
        double* acc;
        if (bid < 186) {
            const int e16 = (bid - 36) * 256 + t;         // cap 38400: exact (150 blocks)
            gsum = sweep16<1600>(p0, e16);
            acc = &g_obj[0];
        } else if (bid < 224) {
            const int e16 = (bid - 186) * 256 + t;        // cap 9600
            if (e16 < 9600) gsum = sweep16<400>(p1, e16);
            acc = &g_obj[1];
        } else {
            const int e16 = (bid - 224) * 256 + t;        // cap 2400
            if (e16 < 2400) gsum = sweep16<100>(p2, e16);
            acc = &g_obj[2];
        }
        float wsum = warpReduceSum(gsum);
        if (lid == 0 && wsum != 0.f) {
            atomicAdd(acc, (double)wsum);
            __threadfence();
        }
        __syncthreads();
    }

    // ---------------- device-side finalize (last block) ----------------
    if (t == 0) {
        __threadfence();
        unsigned old = atomicAdd(&g_done, 1u);
        if (old == gridDim.x - 1) {
            const double cnt[3] = {614400.0, 153600.0, 38400.0};
            double lod = 0.0;
            for (int k = 0; k < 3; k++)
                lod += (g_obj[k] + (double)g_corr[k]) / cnt[k];
            const float lo = (float)lod;
            const float lb = g_box * (1.f / 2304.f);   // N*A*3
            const float lc = g_cls * (1.f / 2304.f);
            const float total = 0.05f * lb + 1.0f * lo + 0.5f * lc;
            float vals[5] = {total, lb, lo, lc, 0.f};
            for (int i = 0; i < out_size; i++)
                out[i] = (i < 5) ? vals[i] : 0.f;
            // reset for next graph replay
            g_box = 0.f;
            g_cls = 0.f;
            for (int k = 0; k < 3; k++) { g_corr[k] = 0.f; g_obj[k] = 0.0; }
            g_done = 0u;
        }
    }
}

extern "C" void kernel_launch(void* const* d_in, const int* in_sizes, int n_in,
                              void* d_out, int out_size) {
    const float* p0 = (const float*)d_in[0];
    const float* p1 = (const float*)d_in[1];
    const float* p2 = (const float*)d_in[2];
    const float* tg = (const float*)d_in[3];
    (void)in_sizes; (void)n_in;

    // 36 target + 150 + 38 + 10 sweep = 234 blocks
    fused_kernel<<<234, 256>>>(p0, p1, p2, tg, (float*)d_out, out_size);
}